// round 3
// baseline (speedup 1.0000x reference)
#include <cuda_runtime.h>
#include <math.h>

#define N_   4
#define H_   64
#define W_   64
#define C_   256
#define CM_  64
#define E_   100     // enc output channels = 25*4
#define HW_  4096    // H*W
#define Q_   65536   // N * 128 * 128 (output pixels)

// ---- scratch (device globals; allocation-free contract) ----
__device__ float g_down[N_ * CM_ * HW_];        // 4 MB   (N,64,64,64)
__device__ float g_kern[N_ * HW_ * E_];         // 6.5 MB (N,H,W,25,4) flattened
__device__ float g_R[C_ * Q_];                  // 64 MB  [c][q], q = n*16384 + ho*128 + wo

// ---- f32x2 packed fp32 helpers (FFMA2 path, exact fp32) ----
__device__ __forceinline__ unsigned long long pk2(float a, float b) {
    unsigned long long r;
    asm("mov.b64 %0, {%1, %2};" : "=l"(r)
        : "r"(__float_as_uint(a)), "r"(__float_as_uint(b)));
    return r;
}
__device__ __forceinline__ void fma2(unsigned long long& d,
                                     unsigned long long a, unsigned long long b) {
    asm("fma.rn.f32x2 %0, %1, %2, %0;" : "+l"(d) : "l"(a), "l"(b));
}
__device__ __forceinline__ float2 up2(unsigned long long v) {
    unsigned int lo, hi;
    asm("mov.b64 {%0, %1}, %2;" : "=r"(lo), "=r"(hi) : "l"(v));
    return make_float2(__uint_as_float(lo), __uint_as_float(hi));
}

// ============================================================
// Kernel 1: 1x1 down conv  (N,256,H,W) -> (N,64,H,W)
// block = (n, row): 64 pixels x 64 out channels, 256 threads
// ============================================================
__global__ __launch_bounds__(256) void k_down(const float* __restrict__ x,
                                              const float* __restrict__ w,
                                              const float* __restrict__ b) {
    __shared__ float Ws[64][65];   // [c][k] chunk
    __shared__ float Xs[64][65];   // [k][p]
    int n = blockIdx.x >> 6, row = blockIdx.x & 63;
    const float* xb = x + ((size_t)n * C_) * HW_ + row * 64;
    int t = threadIdx.x;
    int pg = t & 15, cg = t >> 4;
    float acc[4][4] = {};

    for (int k0 = 0; k0 < 256; k0 += 64) {
        for (int i = t; i < 4096; i += 256) {
            int a = i >> 6, bb = i & 63;
            Xs[a][bb] = xb[(size_t)(k0 + a) * HW_ + bb];
            Ws[a][bb] = w[a * 256 + k0 + bb];
        }
        __syncthreads();
        #pragma unroll 8
        for (int k = 0; k < 64; ++k) {
            float xv[4], wv[4];
            #pragma unroll
            for (int pp = 0; pp < 4; ++pp) xv[pp] = Xs[k][pg * 4 + pp];
            #pragma unroll
            for (int cc = 0; cc < 4; ++cc) wv[cc] = Ws[cg * 4 + cc][k];
            #pragma unroll
            for (int cc = 0; cc < 4; ++cc)
                #pragma unroll
                for (int pp = 0; pp < 4; ++pp)
                    acc[cc][pp] += wv[cc] * xv[pp];
        }
        __syncthreads();
    }
    #pragma unroll
    for (int cc = 0; cc < 4; ++cc) {
        int c = cg * 4 + cc;
        float bias = b[c];
        float4 v = make_float4(acc[cc][0] + bias, acc[cc][1] + bias,
                               acc[cc][2] + bias, acc[cc][3] + bias);
        *(float4*)&g_down[((size_t)(n * CM_ + c)) * HW_ + row * 64 + pg * 4] = v;
    }
}

// ============================================================
// Kernel 2: 3x3 enc conv (64->100) + fused softmax over 25
// block = (n, row); thread = (pixel p, d-subgroup dg) -> softmax is thread-local
// ============================================================
__global__ __launch_bounds__(256) void k_enc(const float* __restrict__ we,
                                             const float* __restrict__ be) {
    __shared__ __align__(16) float Wc[E_ * 96];   // [e][ci*12 + r], r<9 (pad 12 for f4 align)
    __shared__ float Xs[8][3][68];                // [ci][row][w+halo]
    int n = blockIdx.x >> 6, h = blockIdx.x & 63;
    int t = threadIdx.x;
    int p = t & 63, dg = t >> 6;
    float acc[25] = {};

    for (int c0 = 0; c0 < CM_; c0 += 8) {
        for (int i = t; i < E_ * 72; i += 256) {
            int e = i / 72, rem = i % 72, ci = rem / 9, r = rem % 9;
            Wc[e * 96 + ci * 12 + r] = we[e * (CM_ * 9) + (c0 + ci) * 9 + r];
        }
        for (int i = t; i < 8 * 3 * 66; i += 256) {
            int c = i / 198, rem = i % 198, r = rem / 66, wq = rem % 66;
            int hh = h - 1 + r, ww = wq - 1;
            float v = 0.f;
            if (hh >= 0 && hh < 64 && ww >= 0 && ww < 64)
                v = g_down[((size_t)(n * CM_ + c0 + c) * 64 + hh) * 64 + ww];
            Xs[c][r][wq] = v;
        }
        __syncthreads();
        for (int ci = 0; ci < 8; ++ci) {
            float xr[9];
            #pragma unroll
            for (int kh = 0; kh < 3; ++kh)
                #pragma unroll
                for (int kw = 0; kw < 3; ++kw)
                    xr[kh * 3 + kw] = Xs[ci][kh][p + kw];
            #pragma unroll
            for (int kidx = 0; kidx < 25; ++kidx) {
                const float* wr = &Wc[(kidx * 4 + dg) * 96 + ci * 12];
                float4 w0 = *(const float4*)wr;
                float4 w1 = *(const float4*)(wr + 4);
                float w8 = wr[8];
                acc[kidx] += w0.x * xr[0] + w0.y * xr[1] + w0.z * xr[2]
                           + w0.w * xr[3] + w1.x * xr[4] + w1.y * xr[5]
                           + w1.z * xr[6] + w1.w * xr[7] + w8 * xr[8];
            }
        }
        __syncthreads();
    }

    // per-thread softmax over the 25 kidx (same d, same pixel)
    float m = -1e30f;
    #pragma unroll
    for (int k = 0; k < 25; ++k) { acc[k] += be[k * 4 + dg]; m = fmaxf(m, acc[k]); }
    float s = 0.f;
    #pragma unroll
    for (int k = 0; k < 25; ++k) { acc[k] = expf(acc[k] - m); s += acc[k]; }
    float inv = 1.f / s;
    float* kp = &g_kern[((size_t)(n * HW_ + h * 64 + p)) * E_];
    #pragma unroll
    for (int k = 0; k < 25; ++k) kp[k * 4 + dg] = acc[k] * inv;
}

// ============================================================
// Kernel 3: CARAFE reassembly -> g_R[c][q] in pixel-shuffled layout
// block = (n, row); thread = (pixel p, channel subgroup g)
// ============================================================
#define KP_ 101   // kern smem pitch: p*101 mod 32 = p*5 mod 32 -> conflict-free
__global__ __launch_bounds__(256) void k_reasm(const float* __restrict__ x) {
    __shared__ float Ks[64 * KP_];        // 25856 B
    __shared__ float Xs[16 * 5 * 68];     // 21760 B
    int n = blockIdx.x >> 6, h = blockIdx.x & 63;
    int t = threadIdx.x;
    int p = t & 63, g = t >> 6;

    for (int i = t; i < 64 * 100; i += 256) {
        int pp = i / 100, j = i % 100;
        Ks[pp * KP_ + j] = g_kern[((size_t)(n * HW_ + h * 64 + pp)) * E_ + j];
    }

    for (int c0 = 0; c0 < C_; c0 += 16) {
        __syncthreads();   // prev compute done before Xs overwrite
        for (int i = t; i < 16 * 5 * 68; i += 256) {
            int c = i / 340, rem = i % 340, r = rem / 68, wq = rem % 68;
            int hh = h - 2 + r, ww = wq - 2;
            float v = 0.f;
            if (hh >= 0 && hh < 64 && ww >= 0 && ww < 64)
                v = x[((size_t)(n * C_ + c0 + c) * 64 + hh) * 64 + ww];
            Xs[i] = v;
        }
        __syncthreads();

        float acc[4][4] = {};
        const float* kr = &Ks[p * KP_];
        #pragma unroll
        for (int kidx = 0; kidx < 25; ++kidx) {
            int ih = kidx / 5, iw = kidx % 5;
            float kv0 = kr[kidx * 4 + 0], kv1 = kr[kidx * 4 + 1];
            float kv2 = kr[kidx * 4 + 2], kv3 = kr[kidx * 4 + 3];
            #pragma unroll
            for (int cc = 0; cc < 4; ++cc) {
                float xv = Xs[(g * 4 + cc) * 340 + ih * 68 + p + iw];
                acc[cc][0] += xv * kv0;
                acc[cc][1] += xv * kv1;
                acc[cc][2] += xv * kv2;
                acc[cc][3] += xv * kv3;
            }
        }
        #pragma unroll
        for (int cc = 0; cc < 4; ++cc) {
            int c = c0 + g * 4 + cc;
            float* rp = &g_R[(size_t)c * Q_ + n * 16384 + (2 * h) * 128 + 2 * p];
            *(float2*)rp         = make_float2(acc[cc][0], acc[cc][1]);   // d=0,1 -> row 2h
            *(float2*)(rp + 128) = make_float2(acc[cc][2], acc[cc][3]);   // d=2,3 -> row 2h+1
        }
    }
}

// ============================================================
// Kernel 4: 1x1 out conv = GEMM 256x256 @ 65536, f32x2 (FFMA2)
// BM=64 oc, BN=128 q, BK=32; output written directly in d_out layout
// ============================================================
__global__ __launch_bounds__(256) void k_out(const float* __restrict__ w,
                                             const float* __restrict__ b,
                                             float* __restrict__ out) {
    __shared__ unsigned long long Wd[64][32];        // packed (w,w) pairs, 16 KB
    __shared__ __align__(16) float Xs[32][128];      // 16 KB
    int t = threadIdx.x;
    int qbase = blockIdx.x * 128;
    int ocbase = blockIdx.y * 64;
    int tq = t & 31, tc = t >> 5;
    int q0 = tq * 4, oc0 = tc * 8;
    unsigned long long acc[8][2] = {};

    for (int k0 = 0; k0 < 256; k0 += 32) {
        for (int i = t; i < 2048; i += 256) {
            int c = i >> 5, k = i & 31;             // c const per warp -> coalesced gld
            float wv = w[(ocbase + c) * 256 + k0 + k];
            Wd[c][k] = pk2(wv, wv);
        }
        for (int i = t * 4; i < 4096; i += 1024) {
            int k = i >> 7, q = i & 127;
            *(float4*)&Xs[k][q] =
                *(const float4*)&g_R[(size_t)(k0 + k) * Q_ + qbase + q];
        }
        __syncthreads();
        #pragma unroll 8
        for (int k = 0; k < 32; ++k) {
            float4 xv = *(const float4*)&Xs[k][q0];
            unsigned long long xlo = pk2(xv.x, xv.y);
            unsigned long long xhi = pk2(xv.z, xv.w);
            #pragma unroll
            for (int i = 0; i < 8; ++i) {
                unsigned long long w2 = Wd[oc0 + i][k];   // warp-broadcast LDS.64
                fma2(acc[i][0], w2, xlo);
                fma2(acc[i][1], w2, xhi);
            }
        }
        __syncthreads();
    }

    int q = qbase + q0;
    int n = q >> 14, pos = q & 16383;
    #pragma unroll
    for (int i = 0; i < 8; ++i) {
        int oc = ocbase + oc0 + i;
        float bias = b[oc];
        float2 lo = up2(acc[i][0]);
        float2 hi = up2(acc[i][1]);
        float4 v = make_float4(lo.x + bias, lo.y + bias, hi.x + bias, hi.y + bias);
        *(float4*)&out[((size_t)n * 256 + oc) * 16384 + pos] = v;
    }
}

// ============================================================
extern "C" void kernel_launch(void* const* d_in, const int* in_sizes, int n_in,
                              void* d_out, int out_size) {
    const float* x      = (const float*)d_in[0];
    const float* w_down = (const float*)d_in[1];
    const float* b_down = (const float*)d_in[2];
    const float* w_enc  = (const float*)d_in[3];
    const float* b_enc  = (const float*)d_in[4];
    const float* w_out  = (const float*)d_in[5];
    const float* b_out  = (const float*)d_in[6];
    float* out = (float*)d_out;

    k_down <<<N_ * H_, 256>>>(x, w_down, b_down);
    k_enc  <<<N_ * H_, 256>>>(w_enc, b_enc);
    k_reasm<<<N_ * H_, 256>>>(x);
    k_out  <<<dim3(Q_ / 128, C_ / 64), 256>>>(w_out, b_out, out);
}